// round 15
// baseline (speedup 1.0000x reference)
#include <cuda_runtime.h>
#include <cuda_bf16.h>
#include <math.h>
#include <stdint.h>

#define NB 2
#define SEQ 2048
#define DMODEL 1024
#define NHEAD 16
#define DHEAD 64
#define DFF 4096
#define NTOK (NB*SEQ)          // 4096

typedef unsigned short u16;
typedef unsigned int   u32;

// ---------------- scratch (device globals; no runtime allocation) ----------------
// "planes": separate bf16 hi and lo arrays, K-major (contraction dim contiguous)
__device__ __align__(16) u16 g_normH[(size_t)NTOK*DMODEL];
__device__ __align__(16) u16 g_normL[(size_t)NTOK*DMODEL];
__device__ __align__(16) u16 g_qH[(size_t)NTOK*DMODEL];
__device__ __align__(16) u16 g_qL[(size_t)NTOK*DMODEL];
__device__ __align__(16) u16 g_kH[(size_t)NTOK*DMODEL];
__device__ __align__(16) u16 g_kL[(size_t)NTOK*DMODEL];
__device__ __align__(16) u16 g_vH[(size_t)NTOK*DMODEL];
__device__ __align__(16) u16 g_vL[(size_t)NTOK*DMODEL];
__device__ __align__(16) u16 g_vTH[(size_t)2048*2048];   // [b*1024+col][seq]
__device__ __align__(16) u16 g_vTL[(size_t)2048*2048];
__device__ __align__(16) float g_scores[(size_t)NB*NHEAD*SEQ*SEQ];  // 512 MB
__device__ __align__(16) u16 g_pH[(size_t)NB*NHEAD*SEQ*SEQ];        // probs planes
__device__ __align__(16) u16 g_pL[(size_t)NB*NHEAD*SEQ*SEQ];
__device__ __align__(16) u16 g_ctxH[(size_t)NTOK*DMODEL];
__device__ __align__(16) u16 g_ctxL[(size_t)NTOK*DMODEL];
__device__ __align__(16) float g_hidden[(size_t)NTOK*DMODEL];
__device__ __align__(16) float g_ff1[(size_t)NTOK*DFF];
__device__ __align__(16) float g_ff2[(size_t)NTOK*DFF];
__device__ __align__(16) u16 g_ffH[(size_t)NTOK*DFF];
__device__ __align__(16) u16 g_ffL[(size_t)NTOK*DFF];
__device__ int g_bucket[2*SEQ-1];
// transposed (K-major, [n][k]) weight planes
__device__ __align__(16) u16 g_wqTH[(size_t)DMODEL*DMODEL];
__device__ __align__(16) u16 g_wqTL[(size_t)DMODEL*DMODEL];
__device__ __align__(16) u16 g_wkTH[(size_t)DMODEL*DMODEL];
__device__ __align__(16) u16 g_wkTL[(size_t)DMODEL*DMODEL];
__device__ __align__(16) u16 g_wvTH[(size_t)DMODEL*DMODEL];
__device__ __align__(16) u16 g_wvTL[(size_t)DMODEL*DMODEL];
__device__ __align__(16) u16 g_woTH[(size_t)DMODEL*DMODEL];
__device__ __align__(16) u16 g_woTL[(size_t)DMODEL*DMODEL];
__device__ __align__(16) u16 g_w1TH[(size_t)DFF*DMODEL];
__device__ __align__(16) u16 g_w1TL[(size_t)DFF*DMODEL];
__device__ __align__(16) u16 g_w2TH[(size_t)DFF*DMODEL];
__device__ __align__(16) u16 g_w2TL[(size_t)DFF*DMODEL];
__device__ __align__(16) u16 g_woutTH[(size_t)DMODEL*DFF];
__device__ __align__(16) u16 g_woutTL[(size_t)DMODEL*DFF];

// ---------------- small helpers ----------------
__device__ __forceinline__ void split1(float x, u16& h, u16& l)
{
    __nv_bfloat16 hb = __float2bfloat16(x);
    __nv_bfloat16 lb = __float2bfloat16(x - __bfloat162float(hb));
    h = __bfloat16_as_ushort(hb);
    l = __bfloat16_as_ushort(lb);
}
__device__ __forceinline__ void split2u(float e, float o, u32& H, u32& L)
{
    u16 he, le, ho, lo;
    split1(e, he, le); split1(o, ho, lo);
    H = (u32)he | ((u32)ho << 16);
    L = (u32)le | ((u32)lo << 16);
}

__device__ __forceinline__ u32 smem_addr_u32(const void* p)
{
    u32 a;
    asm("{ .reg .u64 t; cvta.to.shared.u64 t, %1; cvt.u32.u64 %0, t; }" : "=r"(a) : "l"(p));
    return a;
}
__device__ __forceinline__ void cp16(u32 smem_dst, const void* gmem_src)
{
    asm volatile("cp.async.cg.shared.global [%0], [%1], 16;\n" :: "r"(smem_dst), "l"(gmem_src));
}
__device__ __forceinline__ void cp_commit()  { asm volatile("cp.async.commit_group;\n" ::: "memory"); }
__device__ __forceinline__ void cp_wait_all(){ asm volatile("cp.async.wait_group 0;\n" ::: "memory"); }

__device__ __forceinline__ void ldsm4(u32& r0, u32& r1, u32& r2, u32& r3, u32 addr)
{
    asm volatile("ldmatrix.sync.aligned.m8n8.x4.shared.b16 {%0,%1,%2,%3}, [%4];"
                 : "=r"(r0), "=r"(r1), "=r"(r2), "=r"(r3) : "r"(addr));
}

__device__ __forceinline__ void mma_bf16(float* d, const u32* a, const u32* b)
{
    asm volatile(
        "mma.sync.aligned.m16n8k16.row.col.f32.bf16.bf16.f32 "
        "{%0,%1,%2,%3}, {%4,%5,%6,%7}, {%8,%9}, {%0,%1,%2,%3};\n"
        : "+f"(d[0]), "+f"(d[1]), "+f"(d[2]), "+f"(d[3])
        : "r"(a[0]), "r"(a[1]), "r"(a[2]), "r"(a[3]),
          "r"(b[0]), "r"(b[1]));
}

// ---------------- split-bf16 ldmatrix GEMM: C = A@B (+Res) ----------------
// CTA tile 128 x NTILE, BK=32, 256 threads = 8 warps (4m x 2n), warp 32 x NTILE/2.
// A planes [m][k], B planes [n][k] (both K-major bf16, hi+lo). Smem rows padded
// to 40 halves (80B) -> ldmatrix conflict-free + 16B aligned. Double-buffered
// cp.async. Per 16-k: 3 MMA terms (hh, lh, hl), fp32 accum.
template<int NTILE, bool PLANES>
__global__ void __launch_bounds__(256, 2)
mma_gemm(const u16* __restrict__ aH, const u16* __restrict__ aL,
         const u16* __restrict__ bH, const u16* __restrict__ bL,
         const float* __restrict__ Res, float* __restrict__ C,
         u32* __restrict__ CH, u32* __restrict__ CL,
         int lda, int ldb, int ldc, int ldcP, int K,
         int ZI,
         long long sAo, long long sAi, long long sBo, long long sBi,
         long long sCo, long long sCi)
{
    constexpr int APLB  = 128 * 80;            // bytes per A plane (128 rows x 80B)
    constexpr int BPLB  = NTILE * 80;
    constexpr int BOFF  = 2 * APLB;            // B planes start
    constexpr int STAGEB = 2 * APLB + 2 * BPLB;
    constexpr int WN    = NTILE / 2;
    constexpr int NT    = NTILE / 16;          // n8 tiles per warp
    constexpr int NBLK  = WN / 32;             // 2 (NTILE=128) or 1 (64)
    constexpr int BITER = (2 * NTILE * 4) / 256;

    extern __shared__ __align__(16) u16 smraw[];
    u32 sdata = smem_addr_u32(smraw);

    int z = blockIdx.z, zo = z / ZI, zi = z - zo * ZI;
    aH += zo*sAo + zi*sAi;  aL += zo*sAo + zi*sAi;
    bH += zo*sBo + zi*sBi;  bL += zo*sBo + zi*sBi;

    int tid = threadIdx.x;
    int lane = tid & 31, wid = tid >> 5;
    int warp_m = wid >> 1, warp_n = wid & 1;
    int g = lane >> 2, t4 = lane & 3;
    int lrow = lane & 15, lk = (lane >> 4) * 8;
    int row0 = blockIdx.y * 128;
    int col0 = blockIdx.x * NTILE;

    float acc[2][NT][4];
    #pragma unroll
    for (int mi = 0; mi < 2; mi++)
        #pragma unroll
        for (int ni = 0; ni < NT; ni++)
            #pragma unroll
            for (int r = 0; r < 4; r++) acc[mi][ni][r] = 0.f;

    auto fill = [&](int buf, int k0) {
        u32 stage = sdata + buf * STAGEB;
        #pragma unroll
        for (int j = 0; j < 4; j++) {                 // A: 1024 16B chunks
            int idx = tid + j * 256;
            int row = idx & 127, c = (idx >> 7) & 3, pl = idx >> 9;
            const u16* src = (pl ? aL : aH) + (size_t)(row0 + row) * lda + k0 + c*8;
            cp16(stage + pl*APLB + row*80 + c*16, src);
        }
        #pragma unroll
        for (int j = 0; j < BITER; j++) {             // B
            int idx = tid + j * 256;
            int row, c, pl;
            if (NTILE == 128) { row = idx & 127; c = (idx >> 7) & 3; pl = idx >> 9; }
            else              { row = idx & 63;  c = (idx >> 6) & 3; pl = idx >> 8; }
            const u16* src = (pl ? bL : bH) + (size_t)(col0 + row) * ldb + k0 + c*8;
            cp16(stage + BOFF + pl*BPLB + row*80 + c*16, src);
        }
    };

    fill(0, 0); cp_commit();
    cp_wait_all();
    __syncthreads();

    int T = K / 32;
    int cur = 0;
    for (int t = 0; t < T; t++) {
        bool more = (t + 1) < T;
        if (more) { fill(cur ^ 1, (t + 1) * 32); cp_commit(); }

        u32 stage = sdata + cur * STAGEB;
        #pragma unroll
        for (int kk = 0; kk < 32; kk += 16) {
            u32 ah[2][4], al[2][4];
            #pragma unroll
            for (int mi = 0; mi < 2; mi++) {
                u32 ro = (u32)(warp_m*32 + mi*16 + lrow) * 80 + (kk + lk) * 2;
                ldsm4(ah[mi][0], ah[mi][1], ah[mi][2], ah[mi][3], stage + ro);
                ldsm4(al[mi][0], al[mi][1], al[mi][2], al[mi][3], stage + APLB + ro);
            }
            #pragma unroll
            for (int nb = 0; nb < NBLK; nb++) {
                u32 bh[4][2], bl[4][2];
                #pragma unroll
                for (int gi = 0; gi < 2; gi++) {
                    u32 ro = (u32)(warp_n*WN + nb*32 + gi*16 + lrow) * 80 + (kk + lk) * 2;
                    u32 t0, t1, t2, t3;
                    ldsm4(t0, t1, t2, t3, stage + BOFF + ro);
                    bh[gi*2  ][0] = t0; bh[gi*2  ][1] = t2;
                    bh[gi*2+1][0] = t1; bh[gi*2+1][1] = t3;
                    ldsm4(t0, t1, t2, t3, stage + BOFF + BPLB + ro);
                    bl[gi*2  ][0] = t0; bl[gi*2  ][1] = t2;
                    bl[gi*2+1][0] = t1; bl[gi*2+1][1] = t3;
                }
                #pragma unroll
                for (int mi = 0; mi < 2; mi++)
                    #pragma unroll
                    for (int nj = 0; nj < 4; nj++) {
                        float* d = acc[mi][nb*4 + nj];
                        mma_bf16(d, ah[mi], bh[nj]);
                        mma_bf16(d, al[mi], bh[nj]);
                        mma_bf16(d, ah[mi], bl[nj]);
                    }
            }
        }

        if (more) cp_wait_all();
        __syncthreads();
        cur ^= 1;
    }

    // epilogue: d0,d1 at (r, c..c+1); d2,d3 at (r+8, c..c+1)
    #pragma unroll
    for (int mi = 0; mi < 2; mi++) {
        #pragma unroll
        for (int ni = 0; ni < NT; ni++) {
            int r = row0 + warp_m*32 + mi*16 + g;
            int c = col0 + warp_n*WN + ni*8 + t4*2;
            float2 v0 = make_float2(acc[mi][ni][0], acc[mi][ni][1]);
            float2 v1 = make_float2(acc[mi][ni][2], acc[mi][ni][3]);
            if (PLANES) {
                u32* CHp = CH + zo*sCo + zi*sCi;
                u32* CLp = CL + zo*sCo + zi*sCi;
                u32 H, L;
                split2u(v0.x, v0.y, H, L);
                CHp[(size_t)r * ldcP + (c >> 1)] = H;
                CLp[(size_t)r * ldcP + (c >> 1)] = L;
                split2u(v1.x, v1.y, H, L);
                CHp[(size_t)(r + 8) * ldcP + (c >> 1)] = H;
                CLp[(size_t)(r + 8) * ldcP + (c >> 1)] = L;
            } else {
                float* Cp = C + zo*sCo + zi*sCi;
                if (Res) {
                    float2 r0 = *reinterpret_cast<const float2*>(Res + (size_t)r * ldc + c);
                    float2 r1 = *reinterpret_cast<const float2*>(Res + (size_t)(r + 8) * ldc + c);
                    v0.x += r0.x; v0.y += r0.y;
                    v1.x += r1.x; v1.y += r1.y;
                }
                *reinterpret_cast<float2*>(Cp + (size_t)r * ldc + c) = v0;
                *reinterpret_cast<float2*>(Cp + (size_t)(r + 8) * ldc + c) = v1;
            }
        }
    }
}

// ---------------- weight transpose-convert: w[k][n] fp32 -> planes [n][k] --------
__global__ void wconv(const float* __restrict__ w, u16* __restrict__ oH,
                      u16* __restrict__ oL, int K, int N)
{
    __shared__ float t[32][33];
    int n0 = blockIdx.x * 32, k0 = blockIdx.y * 32;
    int tx = threadIdx.x, ty = threadIdx.y;
    #pragma unroll
    for (int j = 0; j < 4; j++)
        t[ty + 8*j][tx] = w[(size_t)(k0 + ty + 8*j) * N + n0 + tx];
    __syncthreads();
    #pragma unroll
    for (int j = 0; j < 4; j++) {
        float v = t[tx][ty + 8*j];
        u16 h, l; split1(v, h, l);
        size_t o = (size_t)(n0 + ty + 8*j) * K + k0 + tx;
        oH[o] = h; oL[o] = l;
    }
}

// ---------------- v plane transpose: [b*2048+s][1024] -> [b*1024+c][2048] --------
__global__ void vtrans(const u16* __restrict__ in, u16* __restrict__ out)
{
    __shared__ u16 t[32][33];
    int b = blockIdx.z;
    int c0 = blockIdx.x * 32, s0 = blockIdx.y * 32;
    int tx = threadIdx.x, ty = threadIdx.y;
    #pragma unroll
    for (int j = 0; j < 4; j++)
        t[ty + 8*j][tx] = in[(size_t)(b*2048 + s0 + ty + 8*j) * 1024 + c0 + tx];
    __syncthreads();
    #pragma unroll
    for (int j = 0; j < 4; j++)
        out[(size_t)(b*1024 + c0 + ty + 8*j) * 2048 + s0 + tx] = t[tx][ty + 8*j];
}

// ---------------- RMSNorm -> planes ----------------
__global__ void rmsnorm_kernel(const float* __restrict__ x, const float* __restrict__ w,
                               u32* __restrict__ oH, u32* __restrict__ oL)
{
    int row = blockIdx.x;
    const float2* xr = (const float2*)(x + (size_t)row * DMODEL);
    const float2* w2 = (const float2*)w;
    int tid = threadIdx.x;

    float s = 0.f;
    for (int i = tid; i < DMODEL/2; i += 256) { float2 v = xr[i]; s += v.x*v.x + v.y*v.y; }
    __shared__ float red[256];
    red[tid] = s; __syncthreads();
    for (int st = 128; st > 0; st >>= 1) {
        if (tid < st) red[tid] += red[tid + st];
        __syncthreads();
    }
    float scale = rsqrtf(red[0] / (float)DMODEL + 1e-6f);

    for (int i = tid; i < DMODEL/2; i += 256) {
        float2 v = xr[i]; float2 ww = w2[i];
        u32 H, L; split2u(v.x * scale * ww.x, v.y * scale * ww.y, H, L);
        oH[(size_t)row * 512 + i] = H;
        oL[(size_t)row * 512 + i] = L;
    }
}

// ---------------- T5 relative-position bucket table ----------------
__global__ void bucket_kernel(int* __restrict__ table)
{
    int i = blockIdx.x * blockDim.x + threadIdx.x;
    if (i >= 2*SEQ - 1) return;
    int rel = i - (SEQ - 1);
    int ret = (rel > 0) ? 16 : 0;
    int n = abs(rel);
    int bucket;
    if (n < 8) bucket = n;
    else {
        int vl = 8 + (int)(logf((float)n / 8.0f) / logf(16.0f) * 8.0f);
        bucket = min(vl, 15);
    }
    table[i] = ret + bucket;
}

// ---------------- bias + mask + softmax -> prob planes ----------------
__global__ void softmax_kernel(const float* __restrict__ scores,
                               const float* __restrict__ rel_bias,
                               const int* __restrict__ bucket,
                               const float* __restrict__ mask,
                               u32* __restrict__ pH, u32* __restrict__ pL)
{
    int qv = blockIdx.x, h = blockIdx.y, b = blockIdx.z;
    int tid = threadIdx.x;
    size_t rowbase = (((size_t)(b*NHEAD + h)) * SEQ + qv);
    const float2* row2 = (const float2*)(scores + rowbase * SEQ);

    __shared__ float red[256];

    float2 vals[4];
    float lmax = -1e30f;
    #pragma unroll
    for (int j = 0; j < 4; j++) {
        int kp = tid + j * 256;
        int k0 = 2*kp, k1 = 2*kp + 1;
        float2 v = row2[kp];
        v.x += rel_bias[bucket[k0 - qv + (SEQ-1)] * NHEAD + h]
             + (1.0f - mask[b*SEQ + k0]) * -10000.0f;
        v.y += rel_bias[bucket[k1 - qv + (SEQ-1)] * NHEAD + h]
             + (1.0f - mask[b*SEQ + k1]) * -10000.0f;
        vals[j] = v;
        lmax = fmaxf(lmax, fmaxf(v.x, v.y));
    }
    red[tid] = lmax; __syncthreads();
    for (int st = 128; st > 0; st >>= 1) {
        if (tid < st) red[tid] = fmaxf(red[tid], red[tid + st]);
        __syncthreads();
    }
    float m = red[0];
    __syncthreads();

    float lsum = 0.f;
    #pragma unroll
    for (int j = 0; j < 4; j++) {
        vals[j].x = expf(vals[j].x - m);
        vals[j].y = expf(vals[j].y - m);
        lsum += vals[j].x + vals[j].y;
    }
    red[tid] = lsum; __syncthreads();
    for (int st = 128; st > 0; st >>= 1) {
        if (tid < st) red[tid] += red[tid + st];
        __syncthreads();
    }
    float inv = 1.0f / red[0];

    #pragma unroll
    for (int j = 0; j < 4; j++) {
        int kp = tid + j * 256;
        u32 H, L; split2u(vals[j].x * inv, vals[j].y * inv, H, L);
        pH[rowbase * 1024 + kp] = H;
        pL[rowbase * 1024 + kp] = L;
    }
}

// ---------------- gelu_new(a) * g -> planes ----------------
__global__ void gelumul_kernel(const float* __restrict__ a, const float* __restrict__ g,
                               u32* __restrict__ oH, u32* __restrict__ oL, long long npairs)
{
    long long i = (long long)blockIdx.x * blockDim.x + threadIdx.x;
    if (i >= npairs) return;
    float2 x = ((const float2*)a)[i];
    float2 gg = ((const float2*)g)[i];
    float t0 = tanhf(0.7978845608028654f * (x.x + 0.044715f * x.x * x.x * x.x));
    float t1 = tanhf(0.7978845608028654f * (x.y + 0.044715f * x.y * x.y * x.y));
    u32 H, L;
    split2u(0.5f * x.x * (1.0f + t0) * gg.x, 0.5f * x.y * (1.0f + t1) * gg.y, H, L);
    oH[i] = H; oL[i] = L;
}

// ---------------- host orchestration ----------------
#define DSM_128 (2 * (2*128*80 + 2*128*80))   // 81920
#define DSM_64  (2 * (2*128*80 + 2*64*80))    // 61440

extern "C" void kernel_launch(void* const* d_in, const int* in_sizes, int n_in,
                              void* d_out, int out_size)
{
    const float* hidden   = (const float*)d_in[0];
    const float* mask     = (const float*)d_in[1];
    const float* ln1_w    = (const float*)d_in[2];
    const float* wq       = (const float*)d_in[3];
    const float* wk       = (const float*)d_in[4];
    const float* wv       = (const float*)d_in[5];
    const float* rel_bias = (const float*)d_in[6];
    const float* wo       = (const float*)d_in[7];
    const float* ln2_w    = (const float*)d_in[8];
    const float* w1       = (const float*)d_in[9];
    const float* w2       = (const float*)d_in[10];
    const float* w_out    = (const float*)d_in[11];
    float* out = (float*)d_out;

    cudaFuncSetAttribute(reinterpret_cast<const void*>(&mma_gemm<128,false>),
                         cudaFuncAttributeMaxDynamicSharedMemorySize, DSM_128);
    cudaFuncSetAttribute(reinterpret_cast<const void*>(&mma_gemm<128,true>),
                         cudaFuncAttributeMaxDynamicSharedMemorySize, DSM_128);
    cudaFuncSetAttribute(reinterpret_cast<const void*>(&mma_gemm<64,true>),
                         cudaFuncAttributeMaxDynamicSharedMemorySize, DSM_64);

    void* p;
    #define SYM(T, var, sym) cudaGetSymbolAddress(&p, sym); T* var = (T*)p
    SYM(u16, normH, g_normH);  SYM(u16, normL, g_normL);
    SYM(u16, qH, g_qH);        SYM(u16, qL, g_qL);
    SYM(u16, kH, g_kH);        SYM(u16, kL, g_kL);
    SYM(u16, vH, g_vH);        SYM(u16, vL, g_vL);
    SYM(u16, vTH, g_vTH);      SYM(u16, vTL, g_vTL);
    SYM(float, scores, g_scores);
    SYM(u16, pH, g_pH);        SYM(u16, pL, g_pL);
    SYM(u16, ctxH, g_ctxH);    SYM(u16, ctxL, g_ctxL);
    SYM(float, hid, g_hidden);
    SYM(float, ff1, g_ff1);    SYM(float, ff2, g_ff2);
    SYM(u16, ffH, g_ffH);      SYM(u16, ffL, g_ffL);
    SYM(int, bucket, g_bucket);
    SYM(u16, wqTH, g_wqTH);    SYM(u16, wqTL, g_wqTL);
    SYM(u16, wkTH, g_wkTH);    SYM(u16, wkTL, g_wkTL);
    SYM(u16, wvTH, g_wvTH);    SYM(u16, wvTL, g_wvTL);
    SYM(u16, woTH, g_woTH);    SYM(u16, woTL, g_woTL);
    SYM(u16, w1TH, g_w1TH);    SYM(u16, w1TL, g_w1TL);
    SYM(u16, w2TH, g_w2TH);    SYM(u16, w2TL, g_w2TL);
    SYM(u16, woutTH, g_woutTH);SYM(u16, woutTL, g_woutTL);
    #undef SYM

    dim3 blk32(32, 8);

    // 0. weight transpose-converts
    wconv<<<dim3(32, 32), blk32>>>(wq, wqTH, wqTL, DMODEL, DMODEL);
    wconv<<<dim3(32, 32), blk32>>>(wk, wkTH, wkTL, DMODEL, DMODEL);
    wconv<<<dim3(32, 32), blk32>>>(wv, wvTH, wvTL, DMODEL, DMODEL);
    wconv<<<dim3(32, 32), blk32>>>(wo, woTH, woTL, DMODEL, DMODEL);
    wconv<<<dim3(128, 32), blk32>>>(w1, w1TH, w1TL, DMODEL, DFF);
    wconv<<<dim3(128, 32), blk32>>>(w2, w2TH, w2TL, DMODEL, DFF);
    wconv<<<dim3(32, 128), blk32>>>(w_out, woutTH, woutTL, DFF, DMODEL);

    // 1. RMSNorm #1 -> planes
    rmsnorm_kernel<<<NTOK, 256>>>(hidden, ln1_w, (u32*)normH, (u32*)normL);

    // 2. QKV projections: M=4096, N=1024, K=1024 -> planes
    dim3 gProj(DMODEL/128, NTOK/128, 1);
    mma_gemm<128,true><<<gProj, 256, DSM_128>>>(normH, normL, wqTH, wqTL,
        nullptr, nullptr, (u32*)qH, (u32*)qL,
        DMODEL, DMODEL, 0, 512, DMODEL, 1, 0,0, 0,0, 0,0);
    mma_gemm<128,true><<<gProj, 256, DSM_128>>>(normH, normL, wkTH, wkTL,
        nullptr, nullptr, (u32*)kH, (u32*)kL,
        DMODEL, DMODEL, 0, 512, DMODEL, 1, 0,0, 0,0, 0,0);
    mma_gemm<128,true><<<gProj, 256, DSM_128>>>(normH, normL, wvTH, wvTL,
        nullptr, nullptr, (u32*)vH, (u32*)vL,
        DMODEL, DMODEL, 0, 512, DMODEL, 1, 0,0, 0,0, 0,0);

    // 2b. transpose v planes for P@V (B operand [n=d][k=seq])
    vtrans<<<dim3(32, 64, NB), blk32>>>(vH, vTH);
    vtrans<<<dim3(32, 64, NB), blk32>>>(vL, vTL);

    // 3. bucket table
    bucket_kernel<<<(2*SEQ - 1 + 255)/256, 256>>>(bucket);

    // 4. scores = Q @ K^T per (b,h): M=2048, N=2048, K=64 -> fp32
    const long long QS_o = (long long)SEQ * DMODEL;
    const long long SS2  = (long long)SEQ * SEQ;
    dim3 gScore(SEQ/128, SEQ/128, NB*NHEAD);
    mma_gemm<128,false><<<gScore, 256, DSM_128>>>(qH, qL, kH, kL,
        nullptr, scores, nullptr, nullptr,
        DMODEL, DMODEL, SEQ, 0, DHEAD,
        NHEAD, QS_o, DHEAD, QS_o, DHEAD, (long long)NHEAD*SS2, SS2);

    // 5. bias + mask + softmax -> prob planes
    dim3 gSm(SEQ, NHEAD, NB);
    softmax_kernel<<<gSm, 256>>>(scores, rel_bias, bucket, mask, (u32*)pH, (u32*)pL);

    // 6. ctx = P @ V per (b,h): M=2048, N=64, K=2048 -> ctx planes
    dim3 gPV(1, SEQ/128, NB*NHEAD);
    mma_gemm<64,true><<<gPV, 256, DSM_64>>>(pH, pL, vTH, vTL,
        nullptr, nullptr, (u32*)ctxH, (u32*)ctxL,
        SEQ, SEQ, 0, 512, SEQ,
        NHEAD, (long long)NHEAD*SS2, SS2, (long long)1024*2048, (long long)64*2048,
        (long long)2048*512, 32);

    // 7. hidden = hidden_in + ctx @ wo
    mma_gemm<128,false><<<gProj, 256, DSM_128>>>(ctxH, ctxL, woTH, woTL,
        hidden, hid, nullptr, nullptr,
        DMODEL, DMODEL, DMODEL, 0, DMODEL, 1, 0,0, 0,0, 0,0);

    // 8. RMSNorm #2 -> planes
    rmsnorm_kernel<<<NTOK, 256>>>(hid, ln2_w, (u32*)normH, (u32*)normL);

    // 9. ff1/ff2: M=4096, N=4096, K=1024 -> fp32
    dim3 gFF(DFF/128, NTOK/128, 1);
    mma_gemm<128,false><<<gFF, 256, DSM_128>>>(normH, normL, w1TH, w1TL,
        nullptr, ff1, nullptr, nullptr,
        DMODEL, DMODEL, DFF, 0, DMODEL, 1, 0,0, 0,0, 0,0);
    mma_gemm<128,false><<<gFF, 256, DSM_128>>>(normH, normL, w2TH, w2TL,
        nullptr, ff2, nullptr, nullptr,
        DMODEL, DMODEL, DFF, 0, DMODEL, 1, 0,0, 0,0, 0,0);

    // 10. gelu_new(ff1) * ff2 -> planes
    long long npairs = (long long)NTOK * DFF / 2;
    gelumul_kernel<<<(unsigned)((npairs + 255)/256), 256>>>(ff1, ff2,
        (u32*)ffH, (u32*)ffL, npairs);

    // 11. out = hidden + ffP @ w_out: M=4096, N=1024, K=4096
    mma_gemm<128,false><<<gProj, 256, DSM_128>>>(ffH, ffL, woutTH, woutTL,
        hid, out, nullptr, nullptr,
        DFF, DFF, DMODEL, 0, DFF, 1, 0,0, 0,0, 0,0);
}

// round 16
// speedup vs baseline: 1.2582x; 1.2582x over previous
#include <cuda_runtime.h>
#include <cuda_bf16.h>
#include <math.h>

#define NB 2
#define SEQ 2048
#define DMODEL 1024
#define NHEAD 16
#define DHEAD 64
#define DFF 4096
#define NTOK (NB*SEQ)          // 4096

// ---------------- scratch (device globals; no runtime allocation) ----------------
// packed operand format: uint2{ bf16x2(hi_k_even, hi_k_odd), bf16x2(lo_k_even, lo_k_odd) }
__device__ uint2 g_normP[(size_t)NTOK*(DMODEL/2)];
__device__ uint2 g_qP[(size_t)NTOK*(DMODEL/2)];
__device__ uint2 g_kP[(size_t)NTOK*(DMODEL/2)];
__device__ float g_v[(size_t)NTOK*DMODEL];
__device__ uint2 g_vB[(size_t)(NTOK/2)*DMODEL];
__device__ float g_scores[(size_t)NB*NHEAD*SEQ*SEQ];   // 512 MB (fp32, repacked in place)
__device__ uint2 g_ctxP[(size_t)NTOK*(DMODEL/2)];
__device__ float g_hidden[(size_t)NTOK*DMODEL];
__device__ float g_ff1[(size_t)NTOK*DFF];              // repacked in place by gelumul
__device__ float g_ff2[(size_t)NTOK*DFF];
__device__ int   g_bucket[2*SEQ-1];
// packed weights
__device__ uint2 g_wqB[(size_t)(DMODEL/2)*DMODEL];
__device__ uint2 g_wkB[(size_t)(DMODEL/2)*DMODEL];
__device__ uint2 g_wvB[(size_t)(DMODEL/2)*DMODEL];
__device__ uint2 g_woB[(size_t)(DMODEL/2)*DMODEL];
__device__ uint2 g_w1B[(size_t)(DMODEL/2)*DFF];
__device__ uint2 g_w2B[(size_t)(DMODEL/2)*DFF];
__device__ uint2 g_woutB[(size_t)(DFF/2)*DMODEL];

// ---------------- helpers ----------------
__device__ __forceinline__ uint2 split_pack(float e, float o)
{
    __nv_bfloat16 he = __float2bfloat16(e);
    __nv_bfloat16 ho = __float2bfloat16(o);
    __nv_bfloat16 le = __float2bfloat16(e - __bfloat162float(he));
    __nv_bfloat16 lo = __float2bfloat16(o - __bfloat162float(ho));
    unsigned uh = (unsigned)__bfloat16_as_ushort(he) |
                  ((unsigned)__bfloat16_as_ushort(ho) << 16);
    unsigned ul = (unsigned)__bfloat16_as_ushort(le) |
                  ((unsigned)__bfloat16_as_ushort(lo) << 16);
    return make_uint2(uh, ul);
}

__device__ __forceinline__ void mma_bf16(float* d, const unsigned* a, const unsigned* b)
{
    asm volatile(
        "mma.sync.aligned.m16n8k16.row.col.f32.bf16.bf16.f32 "
        "{%0,%1,%2,%3}, {%4,%5,%6,%7}, {%8,%9}, {%0,%1,%2,%3};\n"
        : "+f"(d[0]), "+f"(d[1]), "+f"(d[2]), "+f"(d[3])
        : "r"(a[0]), "r"(a[1]), "r"(a[2]), "r"(a[3]),
          "r"(b[0]), "r"(b[1]));
}

__device__ __forceinline__ void cp16(void* smem_dst, const void* gmem_src)
{
    unsigned s = (unsigned)__cvta_generic_to_shared(smem_dst);
    asm volatile("cp.async.cg.shared.global [%0], [%1], 16;\n"
                 :: "r"(s), "l"(gmem_src));
}
__device__ __forceinline__ void cp_commit()
{
    asm volatile("cp.async.commit_group;\n" ::: "memory");
}
__device__ __forceinline__ void cp_wait_all()
{
    asm volatile("cp.async.wait_group 0;\n" ::: "memory");
}

// ---------------- gmem fp32 -> packed B-format ([kp][n], pairs across k-rows) ----
__global__ void convert_bfmt(const float* __restrict__ src, uint2* __restrict__ dst,
                             int total, int N)
{
    int idx = blockIdx.x * blockDim.x + threadIdx.x;
    if (idx >= total) return;
    int kp = idx / N, n = idx - kp * N;
    dst[idx] = split_pack(src[(size_t)(2*kp) * N + n], src[(size_t)(2*kp+1) * N + n]);
}

// ---------------- RMSNorm -> packed A-format ----------------
__global__ void rmsnorm_kernel(const float* __restrict__ x, const float* __restrict__ w,
                               uint2* __restrict__ out)
{
    int row = blockIdx.x;
    const float2* xr = (const float2*)(x + (long long)row * DMODEL);
    const float2* w2 = (const float2*)w;
    uint2* orow = out + (long long)row * (DMODEL/2);
    int tid = threadIdx.x;

    float s = 0.f;
    for (int i = tid; i < DMODEL/2; i += 256) {
        float2 v = xr[i];
        s += v.x * v.x + v.y * v.y;
    }
    __shared__ float red[256];
    red[tid] = s; __syncthreads();
    for (int st = 128; st > 0; st >>= 1) {
        if (tid < st) red[tid] += red[tid + st];
        __syncthreads();
    }
    float scale = rsqrtf(red[0] / (float)DMODEL + 1e-6f);

    for (int i = tid; i < DMODEL/2; i += 256) {
        float2 v = xr[i]; float2 ww = w2[i];
        orow[i] = split_pack(v.x * scale * ww.x, v.y * scale * ww.y);
    }
}

// ---------------- T5 relative-position bucket table ----------------
__global__ void bucket_kernel(int* __restrict__ table)
{
    int i = blockIdx.x * blockDim.x + threadIdx.x;
    if (i >= 2*SEQ - 1) return;
    int rel = i - (SEQ - 1);                // k - q
    int ret = (rel > 0) ? 16 : 0;
    int n = abs(rel);
    int bucket;
    if (n < 8) {
        bucket = n;
    } else {
        int vl = 8 + (int)(logf((float)n / 8.0f) / logf(16.0f) * 8.0f);
        bucket = min(vl, 15);
    }
    table[i] = ret + bucket;
}

// ---------------- bias + mask + softmax; writes packed probs in place ----------
__global__ void softmax_kernel(float* __restrict__ scores,
                               const float* __restrict__ rel_bias,   // [32,16]
                               const int* __restrict__ bucket,
                               const float* __restrict__ mask)       // [NB,SEQ]
{
    int qv = blockIdx.x, h = blockIdx.y, b = blockIdx.z;
    int tid = threadIdx.x;
    float* row = scores + (((long long)(b*NHEAD + h)) * SEQ + qv) * SEQ;
    const float2* row2 = (const float2*)row;
    uint2* rowP = (uint2*)row;

    __shared__ float red[256];

    float2 vals[4];
    float lmax = -1e30f;
    #pragma unroll
    for (int j = 0; j < 4; j++) {
        int kp = tid + j * 256;
        int k0 = 2*kp, k1 = 2*kp + 1;
        float2 v = row2[kp];
        v.x += rel_bias[bucket[k0 - qv + (SEQ-1)] * NHEAD + h]
             + (1.0f - mask[b*SEQ + k0]) * -10000.0f;
        v.y += rel_bias[bucket[k1 - qv + (SEQ-1)] * NHEAD + h]
             + (1.0f - mask[b*SEQ + k1]) * -10000.0f;
        vals[j] = v;
        lmax = fmaxf(lmax, fmaxf(v.x, v.y));
    }
    red[tid] = lmax; __syncthreads();
    for (int st = 128; st > 0; st >>= 1) {
        if (tid < st) red[tid] = fmaxf(red[tid], red[tid + st]);
        __syncthreads();
    }
    float m = red[0];
    __syncthreads();

    float lsum = 0.f;
    #pragma unroll
    for (int j = 0; j < 4; j++) {
        vals[j].x = expf(vals[j].x - m);
        vals[j].y = expf(vals[j].y - m);
        lsum += vals[j].x + vals[j].y;
    }
    red[tid] = lsum; __syncthreads();
    for (int st = 128; st > 0; st >>= 1) {
        if (tid < st) red[tid] += red[tid + st];
        __syncthreads();
    }
    float inv = 1.0f / red[0];

    #pragma unroll
    for (int j = 0; j < 4; j++) {
        int kp = tid + j * 256;
        rowP[kp] = split_pack(vals[j].x * inv, vals[j].y * inv);
    }
}

// ---------------- gelu_new(a) * g -> packed in place into a ----------------
__global__ void gelumul_kernel(float* __restrict__ a, const float* __restrict__ g,
                               long long npairs)
{
    long long i = (long long)blockIdx.x * blockDim.x + threadIdx.x;
    if (i >= npairs) return;
    float2 x = ((const float2*)a)[i];
    float2 gg = ((const float2*)g)[i];
    float t0 = tanhf(0.7978845608028654f * (x.x + 0.044715f * x.x * x.x * x.x));
    float t1 = tanhf(0.7978845608028654f * (x.y + 0.044715f * x.y * x.y * x.y));
    float r0 = 0.5f * x.x * (1.0f + t0) * gg.x;
    float r1 = 0.5f * x.y * (1.0f + t1) * gg.y;
    ((uint2*)a)[i] = split_pack(r0, r1);
}

// ---------------- split-bf16 tensor-core GEMM on pre-packed operands -----------
// BM=128, BK=32 (16 kp), BN templated (128/64). 256 threads = 8 warps (4m x 2n).
// A: packed A-format [row][kp]. Smem As[m][kp] stride 20 uint2 (cp.async).
// B !TRANSB: packed B-format [kp][n]. Smem Bs[kp][n] stride BN+4.
// B TRANSB: packed A-format [n][kp]. Smem Bs[n][kp] stride 20.
// Inner loop: 2 x (LDS.64 fragments + 3x mma.bf16 per sub-tile) per barrier.
// PACKOUT: epilogue writes packed A-format (n-pairs) instead of fp32.
template<int BN, bool TRANSB, bool PACKOUT>
__global__ void __launch_bounds__(256, 2)
mma_gemm(const uint2* __restrict__ A, const uint2* __restrict__ B,
         const float* __restrict__ Res, void* __restrict__ Cv,
         int lda, int ldb, int ldc, int ldr, int K,
         int ZI,
         long long sAo, long long sAi, long long sBo, long long sBi,
         long long sCo, long long sCi)
{
    constexpr int ASTR = 20;                   // uint2 stride (16 kp + 4 pad)
    constexpr int BSTR = BN + 4;               // !TRANSB: uint2 per kp-row
    constexpr int AS_BUF = 128 * ASTR;         // 2560 uint2
    constexpr int BS_BUF = TRANSB ? 128 * ASTR : 16 * BSTR;
    constexpr int WN = BN / 2;                 // 64 / 32 cols per warp
    constexpr int NT = WN / 8;                 // 8 / 4 n-tiles per warp
    constexpr int NBLK = NT / 4;               // 2 / 1

    extern __shared__ __align__(16) uint2 dsm[];
    uint2* As = dsm;
    uint2* Bs = dsm + 2 * AS_BUF;

    int z = blockIdx.z;
    int zo = z / ZI, zi = z - zo * ZI;
    A += zo * sAo + zi * sAi;
    B += zo * sBo + zi * sBi;

    int tid = threadIdx.x;
    int lane = tid & 31, wid = tid >> 5;
    int warp_m = wid >> 1, warp_n = wid & 1;
    int g = lane >> 2, t4 = lane & 3;
    int row0 = blockIdx.y * 128;
    int col0 = blockIdx.x * BN;

    float acc[2][NT][4];
    #pragma unroll
    for (int mi = 0; mi < 2; mi++)
        #pragma unroll
        for (int ni = 0; ni < NT; ni++)
            #pragma unroll
            for (int r = 0; r < 4; r++) acc[mi][ni][r] = 0.f;

    auto issueA = [&](int buf, int kp0) {
        #pragma unroll
        for (int it = 0; it < 4; it++) {
            int idx = tid + it * 256;
            int r = idx >> 3, kq = (idx & 7) * 2;
            cp16(&As[buf * AS_BUF + r * ASTR + kq],
                 A + (long long)(row0 + r) * lda + kp0 + kq);
        }
    };
    auto issueB = [&](int buf, int kp0) {
        if (TRANSB) {
            #pragma unroll
            for (int it = 0; it < 4; it++) {
                int idx = tid + it * 256;
                int n = idx >> 3, kq = (idx & 7) * 2;
                cp16(&Bs[buf * BS_BUF + n * ASTR + kq],
                     B + (long long)(col0 + n) * ldb + kp0 + kq);
            }
        } else if (BN == 128) {
            #pragma unroll
            for (int it = 0; it < 4; it++) {
                int idx = tid + it * 256;
                int kp = idx >> 6, n = (idx & 63) * 2;
                cp16(&Bs[buf * BS_BUF + kp * BSTR + n],
                     B + (long long)(kp0 + kp) * ldb + col0 + n);
            }
        } else {
            #pragma unroll
            for (int it = 0; it < 2; it++) {
                int idx = tid + it * 256;
                int kp = idx >> 5, n = (idx & 31) * 2;
                cp16(&Bs[buf * BS_BUF + kp * BSTR + n],
                     B + (long long)(kp0 + kp) * ldb + col0 + n);
            }
        }
    };

    issueA(0, 0); issueB(0, 0); cp_commit();
    cp_wait_all();
    __syncthreads();

    int cur = 0;
    int T = K / 32;                      // 32 k-elements (16 kp) per tile
    for (int t = 0; t < T; t++) {
        bool more = (t + 1) < T;
        if (more) {
            issueA(cur ^ 1, (t + 1) * 16);
            issueB(cur ^ 1, (t + 1) * 16);
            cp_commit();
        }

        #pragma unroll
        for (int kk = 0; kk < 16; kk += 8) {     // two k16 steps per barrier
            uint2 af[2][4];
            #pragma unroll
            for (int mi = 0; mi < 2; mi++) {
                int m = warp_m * 32 + mi * 16 + g;
                const uint2* base = &As[cur * AS_BUF + m * ASTR + kk + t4];
                af[mi][0] = base[0];
                af[mi][1] = base[8 * ASTR];
                af[mi][2] = base[4];
                af[mi][3] = base[8 * ASTR + 4];
            }
            #pragma unroll
            for (int nb = 0; nb < NBLK; nb++) {
                uint2 bf[4][2];
                #pragma unroll
                for (int nj = 0; nj < 4; nj++) {
                    int n = warp_n * WN + (nb * 4 + nj) * 8 + g;
                    if (TRANSB) {
                        bf[nj][0] = Bs[cur * BS_BUF + n * ASTR + kk + t4];
                        bf[nj][1] = Bs[cur * BS_BUF + n * ASTR + kk + t4 + 4];
                    } else {
                        bf[nj][0] = Bs[cur * BS_BUF + (kk + t4    ) * BSTR + n];
                        bf[nj][1] = Bs[cur * BS_BUF + (kk + t4 + 4) * BSTR + n];
                    }
                }
                #pragma unroll
                for (int mi = 0; mi < 2; mi++) {
                    unsigned AH[4] = {af[mi][0].x, af[mi][1].x, af[mi][2].x, af[mi][3].x};
                    unsigned AL[4] = {af[mi][0].y, af[mi][1].y, af[mi][2].y, af[mi][3].y};
                    #pragma unroll
                    for (int nj = 0; nj < 4; nj++) {
                        unsigned BH[2] = {bf[nj][0].x, bf[nj][1].x};
                        unsigned BL[2] = {bf[nj][0].y, bf[nj][1].y};
                        float* d = acc[mi][nb * 4 + nj];
                        mma_bf16(d, AH, BH);
                        mma_bf16(d, AL, BH);
                        mma_bf16(d, AH, BL);
                    }
                }
            }
        }

        if (more) cp_wait_all();
        __syncthreads();
        cur ^= 1;
    }

    // epilogue
    #pragma unroll
    for (int mi = 0; mi < 2; mi++) {
        #pragma unroll
        for (int ni = 0; ni < NT; ni++) {
            int r = row0 + warp_m * 32 + mi * 16 + g;
            int c = col0 + warp_n * WN + ni * 8 + t4 * 2;
            float2 v0 = make_float2(acc[mi][ni][0], acc[mi][ni][1]);
            float2 v1 = make_float2(acc[mi][ni][2], acc[mi][ni][3]);
            if (PACKOUT) {
                uint2* Cp = (uint2*)Cv + zo * sCo + zi * sCi;
                Cp[(long long)r * ldc + (c >> 1)] = split_pack(v0.x, v0.y);
                Cp[(long long)(r + 8) * ldc + (c >> 1)] = split_pack(v1.x, v1.y);
            } else {
                float* C = (float*)Cv + zo * sCo + zi * sCi;
                if (Res) {
                    float2 r0 = *reinterpret_cast<const float2*>(Res + (long long)r * ldr + c);
                    float2 r1 = *reinterpret_cast<const float2*>(Res + (long long)(r + 8) * ldr + c);
                    v0.x += r0.x; v0.y += r0.y;
                    v1.x += r1.x; v1.y += r1.y;
                }
                *reinterpret_cast<float2*>(C + (long long)r * ldc + c) = v0;
                *reinterpret_cast<float2*>(C + (long long)(r + 8) * ldc + c) = v1;
            }
        }
    }
}

// dynamic smem sizes (bytes): uint2 = 8B
#define DSM_128F ((2*128*20 + 2*16*132) * 8)   // 74752
#define DSM_128T ((2*128*20 + 2*128*20) * 8)   // 81920
#define DSM_64F  ((2*128*20 + 2*16*68)  * 8)   // 58368

// ---------------- host orchestration ----------------
extern "C" void kernel_launch(void* const* d_in, const int* in_sizes, int n_in,
                              void* d_out, int out_size)
{
    const float* hidden   = (const float*)d_in[0];
    const float* mask     = (const float*)d_in[1];
    const float* ln1_w    = (const float*)d_in[2];
    const float* wq       = (const float*)d_in[3];
    const float* wk       = (const float*)d_in[4];
    const float* wv       = (const float*)d_in[5];
    const float* rel_bias = (const float*)d_in[6];
    const float* wo       = (const float*)d_in[7];
    const float* ln2_w    = (const float*)d_in[8];
    const float* w1       = (const float*)d_in[9];
    const float* w2       = (const float*)d_in[10];
    const float* w_out    = (const float*)d_in[11];
    float* out = (float*)d_out;

    cudaFuncSetAttribute(reinterpret_cast<const void*>(&mma_gemm<128,false,false>),
                         cudaFuncAttributeMaxDynamicSharedMemorySize, DSM_128F);
    cudaFuncSetAttribute(reinterpret_cast<const void*>(&mma_gemm<128,false,true>),
                         cudaFuncAttributeMaxDynamicSharedMemorySize, DSM_128F);
    cudaFuncSetAttribute(reinterpret_cast<const void*>(&mma_gemm<128,true,false>),
                         cudaFuncAttributeMaxDynamicSharedMemorySize, DSM_128T);
    cudaFuncSetAttribute(reinterpret_cast<const void*>(&mma_gemm<64,false,true>),
                         cudaFuncAttributeMaxDynamicSharedMemorySize, DSM_64F);

    void* p;
    cudaGetSymbolAddress(&p, g_normP);  uint2* normP = (uint2*)p;
    cudaGetSymbolAddress(&p, g_qP);     uint2* qP    = (uint2*)p;
    cudaGetSymbolAddress(&p, g_kP);     uint2* kP    = (uint2*)p;
    cudaGetSymbolAddress(&p, g_v);      float* v     = (float*)p;
    cudaGetSymbolAddress(&p, g_vB);     uint2* vB    = (uint2*)p;
    cudaGetSymbolAddress(&p, g_scores); float* scores= (float*)p;
    cudaGetSymbolAddress(&p, g_ctxP);   uint2* ctxP  = (uint2*)p;
    cudaGetSymbolAddress(&p, g_hidden); float* hid   = (float*)p;
    cudaGetSymbolAddress(&p, g_ff1);    float* ff1   = (float*)p;
    cudaGetSymbolAddress(&p, g_ff2);    float* ff2   = (float*)p;
    cudaGetSymbolAddress(&p, g_bucket); int*   bucket= (int*)p;
    cudaGetSymbolAddress(&p, g_wqB);    uint2* wqB   = (uint2*)p;
    cudaGetSymbolAddress(&p, g_wkB);    uint2* wkB   = (uint2*)p;
    cudaGetSymbolAddress(&p, g_wvB);    uint2* wvB   = (uint2*)p;
    cudaGetSymbolAddress(&p, g_woB);    uint2* woB   = (uint2*)p;
    cudaGetSymbolAddress(&p, g_w1B);    uint2* w1B   = (uint2*)p;
    cudaGetSymbolAddress(&p, g_w2B);    uint2* w2B   = (uint2*)p;
    cudaGetSymbolAddress(&p, g_woutB);  uint2* woutB = (uint2*)p;

    // -- weight conversions (per launch; memory-bound, tiny) --
    int nw = (DMODEL/2) * DMODEL;              // 524288
    convert_bfmt<<<(nw + 255)/256, 256>>>(wq, wqB, nw, DMODEL);
    convert_bfmt<<<(nw + 255)/256, 256>>>(wk, wkB, nw, DMODEL);
    convert_bfmt<<<(nw + 255)/256, 256>>>(wv, wvB, nw, DMODEL);
    convert_bfmt<<<(nw + 255)/256, 256>>>(wo, woB, nw, DMODEL);
    int nff_w = (DMODEL/2) * DFF;              // 2M
    convert_bfmt<<<(nff_w + 255)/256, 256>>>(w1, w1B, nff_w, DFF);
    convert_bfmt<<<(nff_w + 255)/256, 256>>>(w2, w2B, nff_w, DFF);
    int nwo = (DFF/2) * DMODEL;                // 2M
    convert_bfmt<<<(nwo + 255)/256, 256>>>(w_out, woutB, nwo, DMODEL);

    const int LDP = DMODEL/2;                  // 512 uint2 per token row
    const long long SDP = (long long)SEQ * LDP;       // packed per-batch token plane
    const long long SS2 = (long long)SEQ * SEQ;       // score plane (fp32)
    const long long SS2P = SS2 / 2;                   // score plane (uint2)

    // 1. RMSNorm #1 -> packed
    rmsnorm_kernel<<<NTOK, 256>>>(hidden, ln1_w, normP);

    // 2. QKV projections: q,k packed out; v fp32 out
    dim3 gProj(DMODEL/128, NTOK/128, 1);
    mma_gemm<128,false,true><<<gProj, 256, DSM_128F>>>(normP, wqB, nullptr, qP,
        LDP, DMODEL, LDP, 0, DMODEL, 1, 0,0, 0,0, 0,0);
    mma_gemm<128,false,true><<<gProj, 256, DSM_128F>>>(normP, wkB, nullptr, kP,
        LDP, DMODEL, LDP, 0, DMODEL, 1, 0,0, 0,0, 0,0);
    mma_gemm<128,false,false><<<gProj, 256, DSM_128F>>>(normP, wvB, nullptr, v,
        LDP, DMODEL, DMODEL, 0, DMODEL, 1, 0,0, 0,0, 0,0);

    // 2b. v -> B-format (pairs across seq rows; batch boundary at even row, safe)
    int nv = (NTOK/2) * DMODEL;                // 2M
    convert_bfmt<<<(nv + 255)/256, 256>>>(v, vB, nv, DMODEL);

    // 3. bucket table
    bucket_kernel<<<(2*SEQ - 1 + 255)/256, 256>>>(bucket);

    // 4. scores = Q @ K^T per (b,h): A=qP, B=kP (both packed A-format), TRANSB
    dim3 gScore(SEQ/128, SEQ/128, NB*NHEAD);
    mma_gemm<128,true,false><<<gScore, 256, DSM_128T>>>(qP, kP, nullptr, scores,
        LDP, LDP, SEQ, 0, DHEAD,
        NHEAD, SDP, DHEAD/2, SDP, DHEAD/2, (long long)NHEAD*SS2, SS2);

    // 5. bias + mask + softmax -> packed probs in place
    dim3 gSm(SEQ, NHEAD, NB);
    softmax_kernel<<<gSm, 256>>>(scores, rel_bias, bucket, mask);

    // 6. ctx = probs @ V per (b,h): A=scoresP, B=vB -> ctxP (packed out)
    dim3 gPV(1, SEQ/128, NB*NHEAD);
    mma_gemm<64,false,true><<<gPV, 256, DSM_64F>>>((const uint2*)scores, vB, nullptr, ctxP,
        SEQ/2, DMODEL, LDP, 0, SEQ,
        NHEAD, (long long)NHEAD*SS2P, SS2P, (long long)(SEQ/2)*DMODEL, DHEAD,
        SDP, DHEAD/2);

    // 7. hidden = hidden_in + ctx @ wo
    mma_gemm<128,false,false><<<gProj, 256, DSM_128F>>>(ctxP, woB, hidden, hid,
        LDP, DMODEL, DMODEL, DMODEL, DMODEL, 1, 0,0, 0,0, 0,0);

    // 8. RMSNorm #2 -> packed
    rmsnorm_kernel<<<NTOK, 256>>>(hid, ln2_w, normP);

    // 9. ff1 = normed2 @ w1 ; ff2 = normed2 @ w2  (fp32 out)
    dim3 gFF(DFF/128, NTOK/128, 1);
    mma_gemm<128,false,false><<<gFF, 256, DSM_128F>>>(normP, w1B, nullptr, ff1,
        LDP, DFF, DFF, 0, DMODEL, 1, 0,0, 0,0, 0,0);
    mma_gemm<128,false,false><<<gFF, 256, DSM_128F>>>(normP, w2B, nullptr, ff2,
        LDP, DFF, DFF, 0, DMODEL, 1, 0,0, 0,0, 0,0);

    // 10. ff1 = gelu_new(ff1) * ff2 -> packed in place
    long long npairs = (long long)NTOK * DFF / 2;
    gelumul_kernel<<<(unsigned)((npairs + 255)/256), 256>>>(ff1, ff2, npairs);

    // 11. out = hidden + ff1P @ w_out
    mma_gemm<128,false,false><<<gProj, 256, DSM_128F>>>((const uint2*)ff1, woutB, hid, out,
        DFF/2, DMODEL, DMODEL, DMODEL, DFF, 1, 0,0, 0,0, 0,0);
}